// round 13
// baseline (speedup 1.0000x reference)
#include <cuda_runtime.h>
#include <cuda_bf16.h>

// B=2, L=256, D=256. Two launches (no device-wide barrier — robust):
//  K1: GEMM, 128 blocks = lh(2) x b(2) x nt(32 tiles of 16 n), 1024 thr.
//  K2: reverse complex scan, 128 blocks = b(2) x 64 groups of 4 d, 1024 thr.

#define XS_STRIDE 258                       // floats per staged X row
#define XS_BYTES  (128 * XS_STRIDE * 4)     // 132096
#define WK_OFF    XS_BYTES
#define SMEM_DYN  (XS_BYTES + 16384)        // + Wk[128 k2][16 n] float2

__device__ float2 g_A[2 * 256 * 256];       // a coefficients [(b*256+d)*256+l]

__device__ __forceinline__ float2 cmul(float2 a, float2 b) {
    return make_float2(a.x * b.x - a.y * b.y, a.x * b.y + a.y * b.x);
}
__device__ __forceinline__ float2 cadd(float2 a, float2 b) {
    return make_float2(a.x + b.x, a.y + b.y);
}
#define FMA2(acc, x, w) \
    asm("fma.rn.f32x2 %0, %1, %2, %0;" : "+l"(acc) : "l"(x), "l"(w))
#define ADD2(acc, y) \
    asm("add.rn.f32x2 %0, %0, %1;" : "+l"(acc) : "l"(y))

__global__ __launch_bounds__(1024, 1)
void gemm_kernel(const float* __restrict__ X, const float* __restrict__ W) {
    extern __shared__ __align__(16) char smem[];
    const int bid = blockIdx.x;
    const int t   = threadIdx.x;       // 0..1023

    const int lh = bid & 1;            // l half
    const int b  = (bid >> 1) & 1;     // batch
    const int nt = bid >> 2;           // n-tile (16 n = 8 complex d)
    const int n0 = nt * 16;
    const int d0 = nt * 8;

    float*  Xs = (float*)smem;                 // [128][258]
    float2* Wk = (float2*)(smem + WK_OFF);     // [128 k2][16 n]

    const float* Xrows = X + (b * 256 + lh * 128) * 256;

    // stage X half (128 rows x 256 k)
#pragma unroll
    for (int i = 0; i < 8; i++) {
        int e = t + 1024 * i;          // 0..8191
        int l = e >> 6, c = e & 63;
        float4 v = *(const float4*)(Xrows + l * 256 + 4 * c);
        float* p = Xs + l * XS_STRIDE + 4 * c;
        *(float2*)(p)     = make_float2(v.x, v.y);
        *(float2*)(p + 2) = make_float2(v.z, v.w);
    }
    // stage W k-pair-major
#pragma unroll
    for (int i = 0; i < 2; i++) {
        int e = t + 1024 * i;          // 0..2047
        int n = e & 15, k2 = e >> 4;
        Wk[k2 * 16 + n] = *(const float2*)(W + (n0 + n) * 256 + 2 * k2);
    }
    __syncthreads();

    const int lt = t & 127;            // row within half
    const int kh = t >> 7;             // 0..7 k-eighth (16 k2 each)

    unsigned long long acc[16];
#pragma unroll
    for (int n = 0; n < 16; n++) acc[n] = 0ull;

    const float*  xr = Xs + lt * XS_STRIDE + kh * 32;
    const float2* wr = Wk + (kh * 16) * 16;
#pragma unroll
    for (int j = 0; j < 16; j++) {
        unsigned long long x2 = *(const unsigned long long*)(xr + 2 * j);
        const ulonglong2* wp = (const ulonglong2*)(wr + j * 16);
        ulonglong2 w0 = wp[0], w1 = wp[1], w2 = wp[2], w3 = wp[3];
        FMA2(acc[0], x2, w0.x); FMA2(acc[1], x2, w0.y);
        FMA2(acc[2], x2, w1.x); FMA2(acc[3], x2, w1.y);
        FMA2(acc[4], x2, w2.x); FMA2(acc[5], x2, w2.y);
        FMA2(acc[6], x2, w3.x); FMA2(acc[7], x2, w3.y);
        ulonglong2 w4 = wp[4], w5 = wp[5], w6 = wp[6], w7 = wp[7];
        FMA2(acc[8],  x2, w4.x); FMA2(acc[9],  x2, w4.y);
        FMA2(acc[10], x2, w5.x); FMA2(acc[11], x2, w5.y);
        FMA2(acc[12], x2, w6.x); FMA2(acc[13], x2, w6.y);
        FMA2(acc[14], x2, w7.x); FMA2(acc[15], x2, w7.y);
    }
    __syncthreads();   // Xs reads done -> alias as combine scratch

    unsigned long long* scratch = (unsigned long long*)smem;  // [16][7][128]
    if (kh > 0) {
#pragma unroll
        for (int n = 0; n < 16; n++)
            scratch[(n * 7 + (kh - 1)) * 128 + lt] = acc[n];
    }
    __syncthreads();
    if (kh == 0) {
        const int lg = lh * 128 + lt;
#pragma unroll
        for (int p = 0; p < 8; p++) {
            unsigned long long aRe = acc[2 * p], aIm = acc[2 * p + 1];
#pragma unroll
            for (int q = 0; q < 7; q++) {
                ADD2(aRe, scratch[((2 * p) * 7 + q) * 128 + lt]);
                ADD2(aIm, scratch[((2 * p + 1) * 7 + q) * 128 + lt]);
            }
            float r0, r1, i0, i1;
            asm("mov.b64 {%0, %1}, %2;" : "=f"(r0), "=f"(r1) : "l"(aRe));
            asm("mov.b64 {%0, %1}, %2;" : "=f"(i0), "=f"(i1) : "l"(aIm));
            float re = r0 + r1;
            float im = i0 + i1;
            float mag2 = re * re + im * im;
            float s = rsqrtf(mag2) * expf(-mag2);
            g_A[((b * 256 + d0 + p) * 256) + lg] = make_float2(re * s, im * s);
        }
    }
}

__global__ __launch_bounds__(1024, 1)
void scan_kernel(const float* __restrict__ X,
                 const float* __restrict__ h0r, const float* __restrict__ h0i,
                 float* __restrict__ out) {
    __shared__ float  xsr[4 * 256];
    __shared__ float2 wagA[4 * 8], wagY[4 * 8], preY[4 * 8];

    const int bid = blockIdx.x;
    const int t   = threadIdx.x;
    const int b2   = bid >> 6;
    const int dgrp = bid & 63;

    {
        int l = t >> 2, jj = t & 3;
        int d = dgrp * 4 + jj;
        xsr[jj * 256 + l] = (l == 0) ? h0r[d] : X[(b2 * 256 + l - 1) * 256 + d];
    }
    __syncthreads();

    const int g = t >> 8;             // series within block (d = dgrp*4+g)
    const int tl = t & 255;           // reversed index
    const int l = 255 - tl;
    const int lane = t & 31;
    const int w = tl >> 5;
    const int d = dgrp * 4 + g;

    float2 A, Y;
    {
        float2 a = g_A[((b2 * 256 + d) * 256) + l];
        float2 xh;
        xh.x = xsr[g * 256 + l];
        xh.y = (l == 0) ? h0i[d] : 0.f;
        A = a;
        Y = cmul(a, xh);
    }

    const unsigned mask = 0xffffffffu;
#pragma unroll
    for (int o = 1; o < 32; o <<= 1) {
        float2 pA, pY;
        pA.x = __shfl_up_sync(mask, A.x, o);
        pA.y = __shfl_up_sync(mask, A.y, o);
        pY.x = __shfl_up_sync(mask, Y.x, o);
        pY.y = __shfl_up_sync(mask, Y.y, o);
        if (lane >= o) {
            float2 nY = cadd(Y, cmul(A, pY));
            float2 nA = cmul(A, pA);
            Y = nY;
            A = nA;
        }
    }

    if (lane == 31) {
        wagA[g * 8 + w] = A;
        wagY[g * 8 + w] = Y;
    }
    __syncthreads();
    if (tl == 0) {
        float2 pY = make_float2(0.f, 0.f);
#pragma unroll
        for (int w2 = 0; w2 < 8; w2++) {
            preY[g * 8 + w2] = pY;
            pY = cadd(wagY[g * 8 + w2], cmul(wagA[g * 8 + w2], pY));
        }
    }
    __syncthreads();

    float2 Yf = Y;
    if (w > 0) Yf = cadd(Yf, cmul(A, preY[g * 8 + w]));
    float r = Yf.x;
    if (l >= 1)   r += xsr[g * 256 + (l - 1)];
    if (l == 255) r += X[(b2 * 256 + 255) * 256 + d];
    out[(b2 * 256 + l) * 256 + d] = r;
}

extern "C" void kernel_launch(void* const* d_in, const int* in_sizes, int n_in,
                              void* d_out, int out_size) {
    const float* x   = (const float*)d_in[0];
    const float* W   = (const float*)d_in[1];
    const float* h0r = (const float*)d_in[2];
    const float* h0i = (const float*)d_in[3];
    float* out = (float*)d_out;

    cudaFuncSetAttribute(gemm_kernel,
                         cudaFuncAttributeMaxDynamicSharedMemorySize, SMEM_DYN);
    gemm_kernel<<<128, 1024, SMEM_DYN>>>(x, W);
    scan_kernel<<<128, 1024>>>(x, h0r, h0i, out);
}